// round 4
// baseline (speedup 1.0000x reference)
#include <cuda_runtime.h>
#include <cstdint>

// STModel: GCN scatter-agg (scalar features x 48 time-batch slots) + folded
// temporal conv / relu / pool / linear epilogue.
//
// R3: atomic scatter -> CSR-by-dst build + coalesced gather, fused with the
// epilogue (conv/relu/pool/linear). No f32 atomics on the hot path.

#define MAXN 50000
#define MAXE 2000000
#define NB 4
#define NT 12
#define NBT 48
#define NH 32

__device__ float  g_dinv[MAXN];          // deg accumulator -> dinv (rsqrt)
__device__ int    g_cnt[MAXN];           // per-dst edge counts
__device__ int    g_rowstart[MAXN + 1];  // CSR row offsets
__device__ int    g_cursor[MAXN];        // scatter cursors
__device__ int2   g_pairs[MAXE];         // CSR payload: (src, norm as bits)
__device__ float4 g_xt[MAXN * 12];       // x transposed: [N][48]
__device__ unsigned g_oddor;             // !=0 => edge_index int32; ==0 => int64

// ---------------------------------------------------------------------------
__global__ void k_init(int n) {
    int i = blockIdx.x * blockDim.x + threadIdx.x;
    if (i < n) {
        g_dinv[i] = 1.0f;   // self-loop weight preloaded into deg
        g_cnt[i] = 0;
    }
    if (i == 0) g_oddor = 0u;
}

// Detect edge_index dtype: OR the odd 32-bit words of the first 2E words.
// int64 => those are high words of src indices (< 50000) => all zero.
__global__ void k_detect(const unsigned* __restrict__ w, int e) {
    unsigned acc = 0;
    for (int i = blockIdx.x * blockDim.x + threadIdx.x; i < e;
         i += gridDim.x * blockDim.x)
        acc |= w[2 * i + 1];
#pragma unroll
    for (int m = 16; m; m >>= 1) acc |= __shfl_xor_sync(0xffffffffu, acc, m);
    if ((threadIdx.x & 31) == 0 && acc) atomicOr(&g_oddor, acc);
}

// deg accumulation + per-dst edge count histogram.
__global__ void k_deg(const void* __restrict__ ei, const float* __restrict__ ew,
                      int e) {
    int i = blockIdx.x * blockDim.x + threadIdx.x;
    if (i >= e) return;
    int d;
    if (g_oddor) {
        d = ((const int*)ei)[e + i];
    } else {
        d = (int)((const long long*)ei)[e + i];
    }
    atomicAdd(&g_dinv[d], ew[i]);
    atomicAdd(&g_cnt[d], 1);
}

// Single-block exclusive scan over g_cnt -> g_rowstart / g_cursor.
__global__ void __launch_bounds__(1024) k_scan(int n) {
    __shared__ int sp[1024];
    int tid = threadIdx.x;
    int chunk = (n + 1023) / 1024;
    int beg = tid * chunk;
    int end = min(beg + chunk, n);
    int sum = 0;
    for (int i = beg; i < end; i++) sum += g_cnt[i];
    sp[tid] = sum;
    __syncthreads();
    for (int off = 1; off < 1024; off <<= 1) {
        int t = (tid >= off) ? sp[tid - off] : 0;
        __syncthreads();
        sp[tid] += t;
        __syncthreads();
    }
    int run = sp[tid] - sum;   // exclusive prefix
    for (int i = beg; i < end; i++) {
        g_rowstart[i] = run;
        g_cursor[i] = run;
        run += g_cnt[i];
    }
    if (tid == 0) g_rowstart[n] = sp[1023];
}

// x [48, N] -> g_xt [N][48]; finalize dinv = rsqrt(deg).
__global__ void k_trans(const float* __restrict__ x, int n) {
    int node = blockIdx.x * blockDim.x + threadIdx.x;
    if (node >= n) return;
    float dg = g_dinv[node];
    g_dinv[node] = (dg > 0.f) ? rsqrtf(dg) : 0.f;
    float v[NBT];
#pragma unroll
    for (int bt = 0; bt < NBT; bt++) v[bt] = x[bt * n + node];
#pragma unroll
    for (int j = 0; j < 12; j++)
        g_xt[node * 12 + j] =
            make_float4(v[4 * j], v[4 * j + 1], v[4 * j + 2], v[4 * j + 3]);
}

// Scatter edges into CSR order with precomputed norm.
__global__ void __launch_bounds__(256) k_scatter(const void* __restrict__ ei,
                                                 const float* __restrict__ ew,
                                                 int e) {
    int i = blockIdx.x * blockDim.x + threadIdx.x;
    if (i >= e) return;
    int s, d;
    if (g_oddor) {
        const int* p = (const int*)ei;
        s = p[i];
        d = p[e + i];
    } else {
        const long long* p = (const long long*)ei;
        s = (int)p[i];
        d = (int)p[e + i];
    }
    float norm = g_dinv[s] * ew[i] * g_dinv[d];
    int pos = atomicAdd(&g_cursor[d], 1);
    g_pairs[pos] = make_int2(s, __float_as_int(norm));
}

// Fused gather + epilogue. Block = 192 threads = 4 nodes x 48 slots.
__global__ void __launch_bounds__(192) k_fused(const float* __restrict__ cw,
                                               const float* __restrict__ gw,
                                               const float* __restrict__ gb,
                                               const float* __restrict__ cb,
                                               const float* __restrict__ lw,
                                               const float* __restrict__ lb,
                                               float* __restrict__ out, int n) {
    __shared__ float sA0[NH], sA1[NH], sA2[NH], sC0[NH], sC2[NH], sB[NH], sL[NH];
    __shared__ float ss[4][NBT];
    __shared__ float sred[4][NB];
    int tid = threadIdx.x;

    // Fold conv_w with gcn_w/gcn_b (tiny; 96 threads).
    if (tid < 96) {
        int o = tid / 3, k = tid % 3;
        float a = 0.f, c = 0.f;
#pragma unroll
        for (int i = 0; i < NH; i++) {
            float w = cw[o * (NH * 3) + i * 3 + k];
            a = fmaf(w, gw[i], a);
            c = fmaf(w, gb[i], c);
        }
        if (k == 0) { sA0[o] = a; sC0[o] = c; }
        else if (k == 1) { sA1[o] = a; sB[o] = cb[o] + c; sL[o] = lw[o]; }
        else { sA2[o] = a; sC2[o] = c; }
    }
    if (tid < 16) sred[tid >> 2][tid & 3] = 0.f;

    int nl = tid / NBT, j = tid % NBT;
    int node = blockIdx.x * 4 + nl;
    const float* xtf = (const float*)g_xt;

    float sval = 0.f;
    if (node < n) {
        float di = g_dinv[node];
        sval = di * di * xtf[node * NBT + j];   // self-loop term
        int e = g_rowstart[node];
        int end = g_rowstart[node + 1];
        // 2-wide for MLP
        for (; e + 1 < end; e += 2) {
            int2 p0 = g_pairs[e];
            int2 p1 = g_pairs[e + 1];
            float x0 = xtf[p0.x * NBT + j];
            float x1 = xtf[p1.x * NBT + j];
            sval = fmaf(__int_as_float(p0.y), x0, sval);
            sval = fmaf(__int_as_float(p1.y), x1, sval);
        }
        if (e < end) {
            int2 p0 = g_pairs[e];
            sval = fmaf(__int_as_float(p0.y), xtf[p0.x * NBT + j], sval);
        }
    }
    ss[nl][j] = sval;
    __syncthreads();

    // Epilogue: thread (nl, b=j/12, t=j%12) accumulates its t's contribution.
    if (node < n) {
        int b = j / NT, t = j % NT;
        const float* s = &ss[nl][b * NT];
        float st = s[t];
        float sm = (t > 0) ? s[t - 1] : 0.f;
        float sp = (t < NT - 1) ? s[t + 1] : 0.f;
        float acc = 0.f;
#pragma unroll
        for (int o = 0; o < NH; o++) {
            float z = fmaf(sA1[o], st, sB[o]);
            if (t > 0) z = fmaf(sA0[o], sm, z + sC0[o]);
            if (t < NT - 1) z = fmaf(sA2[o], sp, z + sC2[o]);
            acc = fmaf(sL[o], fmaxf(z, 0.f), acc);
        }
        atomicAdd(&sred[nl][b], acc);
    }
    __syncthreads();

    if (tid < 16) {
        int nl2 = tid >> 2, b = tid & 3;
        int node2 = blockIdx.x * 4 + nl2;
        if (node2 < n)
            out[b * n + node2] = fmaf(sred[nl2][b], 1.0f / (float)NT, lb[0]);
    }
}

// ---------------------------------------------------------------------------
extern "C" void kernel_launch(void* const* d_in, const int* in_sizes, int n_in,
                              void* d_out, int out_size) {
    const float* x  = (const float*)d_in[0];
    const void*  ei = d_in[1];
    const float* ew = (const float*)d_in[2];
    const float* gw = (const float*)d_in[3];
    const float* gb = (const float*)d_in[4];
    const float* cw = (const float*)d_in[5];
    const float* cb = (const float*)d_in[6];
    const float* lw = (const float*)d_in[7];
    const float* lb = (const float*)d_in[8];
    float* out = (float*)d_out;

    int N = in_sizes[0] / NBT;
    if (N > MAXN) N = MAXN;
    int E = in_sizes[2];
    if (E > MAXE) E = MAXE;

    int th = 256;
    k_init<<<(N + th - 1) / th, th>>>(N);
    k_detect<<<256, 256>>>((const unsigned*)ei, E);
    k_deg<<<(E + th - 1) / th, th>>>(ei, ew, E);
    k_scan<<<1, 1024>>>(N);
    k_trans<<<(N + 127) / 128, 128>>>(x, N);
    k_scatter<<<(E + th - 1) / th, th>>>(ei, ew, E);
    k_fused<<<(N + 3) / 4, 192>>>(cw, gw, gb, cb, lw, lb, out, N);
}

// round 5
// speedup vs baseline: 1.3308x; 1.3308x over previous
#include <cuda_runtime.h>
#include <cstdint>

// STModel: GCN scatter-agg (scalar x 48 time-batch slots) + folded epilogue.
// R4: parallel 3-kernel scan (was 78us single-block); float-deg atomics
// removed (deg summed from CSR rows); 4-wide unrolled gather.

#define MAXN 50000
#define MAXE 2000000
#define NB 4
#define NT 12
#define NBT 48
#define NH 32
#define SCB 512

__device__ float  g_dinv[MAXN];          // rsqrt(1 + sum w) per node
__device__ int    g_cnt[MAXN];           // per-dst edge counts
__device__ int    g_rowstart[MAXN + 1];  // CSR row offsets
__device__ int    g_cursor[MAXN];        // scatter cursors
__device__ int2   g_pairs[MAXE];         // CSR payload: (src, w as bits)
__device__ float4 g_xt[MAXN * 12];       // x transposed: [N][48]
__device__ int    g_bsum[128];           // scan block sums
__device__ int    g_boff[128];           // scan block offsets
__device__ unsigned g_oddor;             // !=0 => int32 edge_index; ==0 => int64

// ---------------------------------------------------------------------------
__global__ void k_init(int n) {
    int i = blockIdx.x * blockDim.x + threadIdx.x;
    if (i < n) g_cnt[i] = 0;
    if (i == 0) g_oddor = 0u;
}

// Detect dtype from first min(e,8192) index slots: int64 => high words all 0.
__global__ void k_detect(const unsigned* __restrict__ w, int e) {
    int lim = min(e, 8192);
    unsigned acc = 0;
    for (int i = blockIdx.x * blockDim.x + threadIdx.x; i < lim;
         i += gridDim.x * blockDim.x)
        acc |= w[2 * i + 1];
#pragma unroll
    for (int m = 16; m; m >>= 1) acc |= __shfl_xor_sync(0xffffffffu, acc, m);
    if ((threadIdx.x & 31) == 0 && acc) atomicOr(&g_oddor, acc);
}

// Per-dst edge count histogram (int atomics only).
__global__ void k_hist(const void* __restrict__ ei, int e) {
    int i = blockIdx.x * blockDim.x + threadIdx.x;
    if (i >= e) return;
    int d;
    if (g_oddor) d = ((const int*)ei)[e + i];
    else         d = (int)((const long long*)ei)[e + i];
    atomicAdd(&g_cnt[d], 1);
}

// ---- 3-stage parallel exclusive scan over g_cnt ---------------------------
__global__ void __launch_bounds__(SCB) k_scanA(int n) {
    __shared__ int sp[SCB];
    int i = blockIdx.x * SCB + threadIdx.x;
    sp[threadIdx.x] = (i < n) ? g_cnt[i] : 0;
    __syncthreads();
    for (int off = SCB / 2; off > 0; off >>= 1) {
        if (threadIdx.x < off) sp[threadIdx.x] += sp[threadIdx.x + off];
        __syncthreads();
    }
    if (threadIdx.x == 0) g_bsum[blockIdx.x] = sp[0];
}

__global__ void __launch_bounds__(128) k_scanB(int nb) {
    __shared__ int sp[128];
    int tid = threadIdx.x;
    int v = (tid < nb) ? g_bsum[tid] : 0;
    sp[tid] = v;
    __syncthreads();
    for (int off = 1; off < 128; off <<= 1) {
        int t = (tid >= off) ? sp[tid - off] : 0;
        __syncthreads();
        sp[tid] += t;
        __syncthreads();
    }
    g_boff[tid] = sp[tid] - v;   // exclusive
}

__global__ void __launch_bounds__(SCB) k_scanC(int n) {
    __shared__ int sp[SCB];
    int tid = threadIdx.x;
    int i = blockIdx.x * SCB + tid;
    int v = (i < n) ? g_cnt[i] : 0;
    sp[tid] = v;
    __syncthreads();
    for (int off = 1; off < SCB; off <<= 1) {
        int t = (tid >= off) ? sp[tid - off] : 0;
        __syncthreads();
        sp[tid] += t;
        __syncthreads();
    }
    int excl = sp[tid] - v + g_boff[blockIdx.x];
    if (i < n) {
        g_rowstart[i] = excl;
        g_cursor[i] = excl;
        if (i == n - 1) g_rowstart[n] = excl + v;
    }
}

// x [48, N] -> g_xt [N][48].
__global__ void k_trans(const float* __restrict__ x, int n) {
    int node = blockIdx.x * blockDim.x + threadIdx.x;
    if (node >= n) return;
    float v[NBT];
#pragma unroll
    for (int bt = 0; bt < NBT; bt++) v[bt] = x[bt * n + node];
#pragma unroll
    for (int j = 0; j < 12; j++)
        g_xt[node * 12 + j] =
            make_float4(v[4 * j], v[4 * j + 1], v[4 * j + 2], v[4 * j + 3]);
}

// Scatter (src, w) into CSR order.
__global__ void __launch_bounds__(256) k_scatter(const void* __restrict__ ei,
                                                 const float* __restrict__ ew,
                                                 int e) {
    int i = blockIdx.x * blockDim.x + threadIdx.x;
    if (i >= e) return;
    int s, d;
    if (g_oddor) {
        const int* p = (const int*)ei;
        s = p[i];
        d = p[e + i];
    } else {
        const long long* p = (const long long*)ei;
        s = (int)p[i];
        d = (int)p[e + i];
    }
    int pos = atomicAdd(&g_cursor[d], 1);
    g_pairs[pos] = make_int2(s, __float_as_int(ew[i]));
}

// deg[d] = 1 + sum_row w  ->  dinv = rsqrt.  One warp per node, coalesced.
__global__ void __launch_bounds__(256) k_degsum(int n) {
    int gid = blockIdx.x * blockDim.x + threadIdx.x;
    int node = gid >> 5, lane = gid & 31;
    if (node >= n) return;
    int beg = g_rowstart[node], end = g_rowstart[node + 1];
    float s = 0.f;
    for (int e = beg + lane; e < end; e += 32)
        s += __int_as_float(g_pairs[e].y);
#pragma unroll
    for (int m = 16; m; m >>= 1) s += __shfl_xor_sync(0xffffffffu, s, m);
    if (lane == 0) g_dinv[node] = rsqrtf(1.0f + s);
}

// Fused gather + epilogue. Block = 192 threads = 4 nodes x 48 slots.
__global__ void __launch_bounds__(192) k_fused(const float* __restrict__ cw,
                                               const float* __restrict__ gw,
                                               const float* __restrict__ gb,
                                               const float* __restrict__ cb,
                                               const float* __restrict__ lw,
                                               const float* __restrict__ lb,
                                               float* __restrict__ out, int n) {
    __shared__ float sA0[NH], sA1[NH], sA2[NH], sC0[NH], sC2[NH], sB[NH], sL[NH];
    __shared__ float ss[4][NBT];
    __shared__ float sred[4][NB];
    int tid = threadIdx.x;

    if (tid < 96) {
        int o = tid / 3, k = tid % 3;
        float a = 0.f, c = 0.f;
#pragma unroll
        for (int i = 0; i < NH; i++) {
            float w = cw[o * (NH * 3) + i * 3 + k];
            a = fmaf(w, gw[i], a);
            c = fmaf(w, gb[i], c);
        }
        if (k == 0) { sA0[o] = a; sC0[o] = c; }
        else if (k == 1) { sA1[o] = a; sB[o] = cb[o] + c; sL[o] = lw[o]; }
        else { sA2[o] = a; sC2[o] = c; }
    }
    if (tid < 16) sred[tid >> 2][tid & 3] = 0.f;

    int nl = tid / NBT, j = tid % NBT;
    int node = blockIdx.x * 4 + nl;
    const float* xtf = (const float*)g_xt;

    float sval = 0.f;
    if (node < n) {
        float did = g_dinv[node];
        float acc = did * xtf[node * NBT + j];   // self-loop (dinv^2 after scale)
        int e = g_rowstart[node];
        int end = g_rowstart[node + 1];
        for (; e + 3 < end; e += 4) {            // 12 independent loads in flight
            int2 p0 = g_pairs[e],     p1 = g_pairs[e + 1];
            int2 p2 = g_pairs[e + 2], p3 = g_pairs[e + 3];
            float m0 = g_dinv[p0.x] * __int_as_float(p0.y);
            float m1 = g_dinv[p1.x] * __int_as_float(p1.y);
            float m2 = g_dinv[p2.x] * __int_as_float(p2.y);
            float m3 = g_dinv[p3.x] * __int_as_float(p3.y);
            float x0 = xtf[p0.x * NBT + j];
            float x1 = xtf[p1.x * NBT + j];
            float x2 = xtf[p2.x * NBT + j];
            float x3 = xtf[p3.x * NBT + j];
            acc = fmaf(m0, x0, acc);
            acc = fmaf(m1, x1, acc);
            acc = fmaf(m2, x2, acc);
            acc = fmaf(m3, x3, acc);
        }
        for (; e < end; e++) {
            int2 p = g_pairs[e];
            acc = fmaf(g_dinv[p.x] * __int_as_float(p.y),
                       xtf[p.x * NBT + j], acc);
        }
        sval = did * acc;
    }
    ss[nl][j] = sval;
    __syncthreads();

    if (node < n) {
        int b = j / NT, t = j % NT;
        const float* s = &ss[nl][b * NT];
        float st = s[t];
        float sm = (t > 0) ? s[t - 1] : 0.f;
        float sp = (t < NT - 1) ? s[t + 1] : 0.f;
        float acc = 0.f;
#pragma unroll
        for (int o = 0; o < NH; o++) {
            float z = fmaf(sA1[o], st, sB[o]);
            if (t > 0) z = fmaf(sA0[o], sm, z + sC0[o]);
            if (t < NT - 1) z = fmaf(sA2[o], sp, z + sC2[o]);
            acc = fmaf(sL[o], fmaxf(z, 0.f), acc);
        }
        atomicAdd(&sred[nl][b], acc);
    }
    __syncthreads();

    if (tid < 16) {
        int nl2 = tid >> 2, b = tid & 3;
        int node2 = blockIdx.x * 4 + nl2;
        if (node2 < n)
            out[b * n + node2] = fmaf(sred[nl2][b], 1.0f / (float)NT, lb[0]);
    }
}

// ---------------------------------------------------------------------------
extern "C" void kernel_launch(void* const* d_in, const int* in_sizes, int n_in,
                              void* d_out, int out_size) {
    const float* x  = (const float*)d_in[0];
    const void*  ei = d_in[1];
    const float* ew = (const float*)d_in[2];
    const float* gw = (const float*)d_in[3];
    const float* gb = (const float*)d_in[4];
    const float* cw = (const float*)d_in[5];
    const float* cb = (const float*)d_in[6];
    const float* lw = (const float*)d_in[7];
    const float* lb = (const float*)d_in[8];
    float* out = (float*)d_out;

    int N = in_sizes[0] / NBT;
    if (N > MAXN) N = MAXN;
    int E = in_sizes[2];
    if (E > MAXE) E = MAXE;
    int nb = (N + SCB - 1) / SCB;

    int th = 256;
    k_init<<<(N + th - 1) / th, th>>>(N);
    k_detect<<<32, 256>>>((const unsigned*)ei, E);
    k_hist<<<(E + th - 1) / th, th>>>(ei, E);
    k_scanA<<<nb, SCB>>>(N);
    k_scanB<<<1, 128>>>(nb);
    k_scanC<<<nb, SCB>>>(N);
    k_trans<<<(N + 127) / 128, 128>>>(x, N);
    k_scatter<<<(E + th - 1) / th, th>>>(ei, ew, E);
    k_degsum<<<(N * 32 + th - 1) / th, th>>>(N);
    k_fused<<<(N + 3) / 4, 192>>>(cw, gw, gb, cb, lw, lb, out, N);
}

// round 6
// speedup vs baseline: 1.4642x; 1.1002x over previous
#include <cuda_runtime.h>
#include <cstdint>

// STModel: GCN scatter-agg (scalar x 48 time-batch slots) + folded epilogue.
// R5: smem-staged CSR gather (each edge's (src,norm) loaded ONCE per node,
// not once per 48 slot-threads); norm precomputed at scatter; parallel scan.

#define MAXN 50000
#define MAXE 2000000
#define NB 4
#define NT 12
#define NBT 48
#define NH 32
#define SCB 512
#define GCH 32     // gather smem chunk (edges)

__device__ float  g_dinv[MAXN];          // deg accumulator -> rsqrt(deg)
__device__ int    g_cnt[MAXN];           // per-dst edge counts
__device__ int    g_rowstart[MAXN + 1];  // CSR row offsets
__device__ int    g_cursor[MAXN];        // scatter cursors
__device__ int2   g_pairs[MAXE];         // CSR payload: (src, dinv[s]*w bits)
__device__ float4 g_xt[MAXN * 12];       // x transposed: [N][48]
__device__ int    g_bsum[128];           // scan block sums
__device__ int    g_boff[128];           // scan block offsets
__device__ unsigned g_oddor;             // !=0 => int32 edge_index; ==0 => int64

// ---------------------------------------------------------------------------
__global__ void k_init(int n) {
    int i = blockIdx.x * blockDim.x + threadIdx.x;
    if (i < n) {
        g_cnt[i] = 0;
        g_dinv[i] = 1.0f;   // self-loop weight preloaded into deg
    }
    if (i == 0) g_oddor = 0u;
}

// Detect dtype from first min(e,8192) index slots: int64 => high words all 0.
__global__ void k_detect(const unsigned* __restrict__ w, int e) {
    int lim = min(e, 8192);
    unsigned acc = 0;
    for (int i = blockIdx.x * blockDim.x + threadIdx.x; i < lim;
         i += gridDim.x * blockDim.x)
        acc |= w[2 * i + 1];
#pragma unroll
    for (int m = 16; m; m >>= 1) acc |= __shfl_xor_sync(0xffffffffu, acc, m);
    if ((threadIdx.x & 31) == 0 && acc) atomicOr(&g_oddor, acc);
}

// Histogram + degree accumulation.
__global__ void k_hist(const void* __restrict__ ei, const float* __restrict__ ew,
                       int e) {
    int i = blockIdx.x * blockDim.x + threadIdx.x;
    if (i >= e) return;
    int d;
    if (g_oddor) d = ((const int*)ei)[e + i];
    else         d = (int)((const long long*)ei)[e + i];
    atomicAdd(&g_cnt[d], 1);
    atomicAdd(&g_dinv[d], ew[i]);
}

__global__ void k_rsq(int n) {
    int i = blockIdx.x * blockDim.x + threadIdx.x;
    if (i < n) {
        float dg = g_dinv[i];
        g_dinv[i] = (dg > 0.f) ? rsqrtf(dg) : 0.f;
    }
}

// ---- 3-stage parallel exclusive scan over g_cnt ---------------------------
__global__ void __launch_bounds__(SCB) k_scanA(int n) {
    __shared__ int sp[SCB];
    int i = blockIdx.x * SCB + threadIdx.x;
    sp[threadIdx.x] = (i < n) ? g_cnt[i] : 0;
    __syncthreads();
    for (int off = SCB / 2; off > 0; off >>= 1) {
        if (threadIdx.x < off) sp[threadIdx.x] += sp[threadIdx.x + off];
        __syncthreads();
    }
    if (threadIdx.x == 0) g_bsum[blockIdx.x] = sp[0];
}

__global__ void __launch_bounds__(128) k_scanB(int nb) {
    __shared__ int sp[128];
    int tid = threadIdx.x;
    int v = (tid < nb) ? g_bsum[tid] : 0;
    sp[tid] = v;
    __syncthreads();
    for (int off = 1; off < 128; off <<= 1) {
        int t = (tid >= off) ? sp[tid - off] : 0;
        __syncthreads();
        sp[tid] += t;
        __syncthreads();
    }
    g_boff[tid] = sp[tid] - v;
}

__global__ void __launch_bounds__(SCB) k_scanC(int n) {
    __shared__ int sp[SCB];
    int tid = threadIdx.x;
    int i = blockIdx.x * SCB + tid;
    int v = (i < n) ? g_cnt[i] : 0;
    sp[tid] = v;
    __syncthreads();
    for (int off = 1; off < SCB; off <<= 1) {
        int t = (tid >= off) ? sp[tid - off] : 0;
        __syncthreads();
        sp[tid] += t;
        __syncthreads();
    }
    int excl = sp[tid] - v + g_boff[blockIdx.x];
    if (i < n) {
        g_rowstart[i] = excl;
        g_cursor[i] = excl;
        if (i == n - 1) g_rowstart[n] = excl + v;
    }
}

// x [48, N] -> g_xt [N][48].
__global__ void k_trans(const float* __restrict__ x, int n) {
    int node = blockIdx.x * blockDim.x + threadIdx.x;
    if (node >= n) return;
    float v[NBT];
#pragma unroll
    for (int bt = 0; bt < NBT; bt++) v[bt] = x[bt * n + node];
#pragma unroll
    for (int j = 0; j < 12; j++)
        g_xt[node * 12 + j] =
            make_float4(v[4 * j], v[4 * j + 1], v[4 * j + 2], v[4 * j + 3]);
}

// Scatter (src, dinv[s]*w) into CSR order.
__global__ void __launch_bounds__(256) k_scatter(const void* __restrict__ ei,
                                                 const float* __restrict__ ew,
                                                 int e) {
    int i = blockIdx.x * blockDim.x + threadIdx.x;
    if (i >= e) return;
    int s, d;
    if (g_oddor) {
        const int* p = (const int*)ei;
        s = p[i];
        d = p[e + i];
    } else {
        const long long* p = (const long long*)ei;
        s = (int)p[i];
        d = (int)p[e + i];
    }
    float nm = g_dinv[s] * ew[i];
    int pos = atomicAdd(&g_cursor[d], 1);
    g_pairs[pos] = make_int2(s, __float_as_int(nm));
}

// Fused gather + epilogue. Block = 192 threads = 4 nodes x 48 slots.
// Edge (src,norm) chunks are staged in smem: loaded once, consumed by 48.
__global__ void __launch_bounds__(192) k_fused(const float* __restrict__ cw,
                                               const float* __restrict__ gw,
                                               const float* __restrict__ gb,
                                               const float* __restrict__ cb,
                                               const float* __restrict__ lw,
                                               const float* __restrict__ lb,
                                               float* __restrict__ out, int n) {
    __shared__ float sA0[NH], sA1[NH], sA2[NH], sC0[NH], sC2[NH], sB[NH], sL[NH];
    __shared__ int2  spair[4][GCH];
    __shared__ float ss[4][NBT];
    __shared__ float sred[4][NB];
    int tid = threadIdx.x;

    if (tid < 96) {
        int o = tid / 3, k = tid % 3;
        float a = 0.f, c = 0.f;
#pragma unroll
        for (int i = 0; i < NH; i++) {
            float w = cw[o * (NH * 3) + i * 3 + k];
            a = fmaf(w, gw[i], a);
            c = fmaf(w, gb[i], c);
        }
        if (k == 0) { sA0[o] = a; sC0[o] = c; }
        else if (k == 1) { sA1[o] = a; sB[o] = cb[o] + c; sL[o] = lw[o]; }
        else { sA2[o] = a; sC2[o] = c; }
    }
    if (tid < 16) sred[tid >> 2][tid & 3] = 0.f;

    int nl = tid / NBT, j = tid % NBT;
    int node = blockIdx.x * 4 + nl;
    const float* xtf = (const float*)g_xt;

    bool live = node < n;
    int e = 0, end = 0;
    float acc = 0.f, acc1 = 0.f, acc2 = 0.f, acc3 = 0.f;
    if (live) {
        e = g_rowstart[node];
        end = g_rowstart[node + 1];
    }
    for (;;) {
        int rem = end - e;
        bool have = live && rem > 0;
        if (!__syncthreads_or(have)) break;
        if (have && j < GCH && j < rem) spair[nl][j] = g_pairs[e + j];
        __syncthreads();
        if (have) {
            int cnt = min(rem, GCH);
            int k = 0;
            for (; k + 3 < cnt; k += 4) {
                int2 p0 = spair[nl][k],     p1 = spair[nl][k + 1];
                int2 p2 = spair[nl][k + 2], p3 = spair[nl][k + 3];
                float x0 = xtf[p0.x * NBT + j];
                float x1 = xtf[p1.x * NBT + j];
                float x2 = xtf[p2.x * NBT + j];
                float x3 = xtf[p3.x * NBT + j];
                acc  = fmaf(__int_as_float(p0.y), x0, acc);
                acc1 = fmaf(__int_as_float(p1.y), x1, acc1);
                acc2 = fmaf(__int_as_float(p2.y), x2, acc2);
                acc3 = fmaf(__int_as_float(p3.y), x3, acc3);
            }
            for (; k < cnt; k++) {
                int2 p = spair[nl][k];
                acc = fmaf(__int_as_float(p.y), xtf[p.x * NBT + j], acc);
            }
        }
        e += GCH;
        __syncthreads();
    }
    if (live) {
        float did = g_dinv[node];
        float total = (acc + acc1) + (acc2 + acc3);
        ss[nl][j] = did * (total + did * xtf[node * NBT + j]);
    }
    __syncthreads();

    if (live) {
        int b = j / NT, t = j % NT;
        const float* s = &ss[nl][b * NT];
        float st = s[t];
        float sm = (t > 0) ? s[t - 1] : 0.f;
        float sp = (t < NT - 1) ? s[t + 1] : 0.f;
        float a2 = 0.f;
#pragma unroll
        for (int o = 0; o < NH; o++) {
            float z = fmaf(sA1[o], st, sB[o]);
            if (t > 0) z = fmaf(sA0[o], sm, z + sC0[o]);
            if (t < NT - 1) z = fmaf(sA2[o], sp, z + sC2[o]);
            a2 = fmaf(sL[o], fmaxf(z, 0.f), a2);
        }
        atomicAdd(&sred[nl][b], a2);
    }
    __syncthreads();

    if (tid < 16) {
        int nl2 = tid >> 2, b = tid & 3;
        int node2 = blockIdx.x * 4 + nl2;
        if (node2 < n)
            out[b * n + node2] = fmaf(sred[nl2][b], 1.0f / (float)NT, lb[0]);
    }
}

// ---------------------------------------------------------------------------
extern "C" void kernel_launch(void* const* d_in, const int* in_sizes, int n_in,
                              void* d_out, int out_size) {
    const float* x  = (const float*)d_in[0];
    const void*  ei = d_in[1];
    const float* ew = (const float*)d_in[2];
    const float* gw = (const float*)d_in[3];
    const float* gb = (const float*)d_in[4];
    const float* cw = (const float*)d_in[5];
    const float* cb = (const float*)d_in[6];
    const float* lw = (const float*)d_in[7];
    const float* lb = (const float*)d_in[8];
    float* out = (float*)d_out;

    int N = in_sizes[0] / NBT;
    if (N > MAXN) N = MAXN;
    int E = in_sizes[2];
    if (E > MAXE) E = MAXE;
    int nb = (N + SCB - 1) / SCB;

    int th = 256;
    k_init<<<(N + th - 1) / th, th>>>(N);
    k_detect<<<32, 256>>>((const unsigned*)ei, E);
    k_hist<<<(E + th - 1) / th, th>>>(ei, ew, E);
    k_rsq<<<(N + th - 1) / th, th>>>(N);
    k_scanA<<<nb, SCB>>>(N);
    k_scanB<<<1, 128>>>(nb);
    k_scanC<<<nb, SCB>>>(N);
    k_trans<<<(N + 127) / 128, 128>>>(x, N);
    k_scatter<<<(E + th - 1) / th, th>>>(ei, ew, E);
    k_fused<<<(N + 3) / 4, 192>>>(cw, gw, gb, cb, lw, lb, out, N);
}